// round 10
// baseline (speedup 1.0000x reference)
#include <cuda_runtime.h>
#include <math.h>
#include <stdint.h>

// Problem constants
#define EMBED   1024
#define BATCH   2
#define SEQ     2048
#define NHEADS  16
#define HD      64
#define SD      32
#define MTOT    (BATCH*SEQ)          // 4096
#define SCALING 0.17677669529663687f // 1/sqrt(32)
#define LAMBDA_INIT 0.2f             // 0.8 - 0.6*exp(0)
#define ONE_MINUS_LI 0.8f

// Scratch (device globals; no runtime allocation allowed)
__device__ float g_Q[(size_t)MTOT * EMBED];   // projected Q (tf32-rounded)
__device__ float g_K[(size_t)MTOT * EMBED];   // projected K (tf32-rounded)
__device__ float g_V[(size_t)MTOT * EMBED];   // projected V (tf32-rounded)
__device__ float g_O[(size_t)MTOT * EMBED];   // attn out   (tf32-rounded)
__device__ float g_xq[(size_t)MTOT * EMBED];  // rounded input query
__device__ float g_xk[(size_t)MTOT * EMBED];  // rounded input key
__device__ float g_xv[(size_t)MTOT * EMBED];  // rounded input value
__device__ float g_w1[3 * 1024 * 1024];       // rounded in_proj_weight
__device__ float g_w2[1024 * 1024];           // rounded out_proj_weight

// ---------------------------------------------------------------------------
// tf32 + cp.async helpers
// ---------------------------------------------------------------------------
__device__ __forceinline__ uint32_t f2tf(float x) {
    uint32_t r;
    asm("cvt.rna.tf32.f32 %0, %1;" : "=r"(r) : "f"(x));
    return r;
}
__device__ __forceinline__ uint4 cvt4(float4 v) {
    return make_uint4(f2tf(v.x), f2tf(v.y), f2tf(v.z), f2tf(v.w));
}
__device__ __forceinline__ void cpasync16(uint32_t smem_addr, const void* gptr) {
    asm volatile("cp.async.cg.shared.global [%0], [%1], 16;"
                 :: "r"(smem_addr), "l"(gptr));
}
#define CP_COMMIT() asm volatile("cp.async.commit_group;")
#define CP_WAIT0()  asm volatile("cp.async.wait_group 0;")

// D += A(16x8) * B(8x8), tf32 inputs, f32 accumulate.
__device__ __forceinline__ void mma8(float* c, const uint32_t* a,
                                     uint32_t b0, uint32_t b1) {
    asm volatile(
        "mma.sync.aligned.m16n8k8.row.col.f32.tf32.tf32.f32 "
        "{%0,%1,%2,%3}, {%4,%5,%6,%7}, {%8,%9}, {%0,%1,%2,%3};"
        : "+f"(c[0]), "+f"(c[1]), "+f"(c[2]), "+f"(c[3])
        : "r"(a[0]), "r"(a[1]), "r"(a[2]), "r"(a[3]), "r"(b0), "r"(b1));
}

// ---------------------------------------------------------------------------
// Elementwise tf32 rounding pass (float4 grid-stride)
// ---------------------------------------------------------------------------
__global__ void round_tf32_kernel(const float4* __restrict__ in,
                                  float4* __restrict__ out, int n4)
{
    int i = blockIdx.x * blockDim.x + threadIdx.x;
    int stride = gridDim.x * blockDim.x;
    for (; i < n4; i += stride) {
        uint4 u = cvt4(in[i]);
        out[i] = *(float4*)&u;
    }
}

// ---------------------------------------------------------------------------
// tf32 GEMM (cp.async double-buffered): C = A[M,K] @ W[N,K]^T + bias
// (unchanged from R6 — isolating the attention change this round)
// ---------------------------------------------------------------------------
#define G_BUF_WORDS (2 * 128 * 36)          // 9216 words per buffer
#define G_SMEM_BYTES (2 * G_BUF_WORDS * 4)  // 73728

template<bool ROUND>
__global__ __launch_bounds__(256, 2) void gemm_tf32_async(
    const float* __restrict__ A, const float* __restrict__ W,
    const float* __restrict__ bias, float* __restrict__ C,
    int M, int N, int K)
{
    extern __shared__ uint32_t gsm[];
    const uint32_t smem_base = (uint32_t)__cvta_generic_to_shared(gsm);

    const int tid  = threadIdx.x;
    const int lane = tid & 31;
    const int warp = tid >> 5;
    const int g = lane >> 2;
    const int q = lane & 3;
    const int wm = warp >> 1;      // 0..3
    const int wn = warp & 1;       // 0..1
    const int m0 = blockIdx.y * 128;
    const int n0 = blockIdx.x * 128;

    const int nchunks = K >> 5;    // K/32

    auto issue = [&](int ck, int buf) {
        const int k0 = ck * 32;
#pragma unroll
        for (int i = 0; i < 4; i++) {
            int idx = tid + i * 256;   // 0..1023
            int row = idx >> 3;        // 0..127
            int kg  = idx & 7;         // 0..7
            uint32_t soff = (uint32_t)(buf * G_BUF_WORDS + row * 36 + kg * 4) * 4;
            cpasync16(smem_base + soff,
                      &A[(size_t)(m0 + row) * K + k0 + kg * 4]);
            cpasync16(smem_base + soff + 128 * 36 * 4,
                      &W[(size_t)(n0 + row) * K + k0 + kg * 4]);
        }
        CP_COMMIT();
    };

    float c[2][8][4];
#pragma unroll
    for (int mf = 0; mf < 2; mf++)
#pragma unroll
        for (int nf = 0; nf < 8; nf++)
#pragma unroll
            for (int i = 0; i < 4; i++) c[mf][nf][i] = 0.f;

    issue(0, 0);

    for (int it = 0; it < nchunks; it++) {
        CP_WAIT0();
        __syncthreads();
        if (it + 1 < nchunks) issue(it + 1, (it + 1) & 1);

        const uint32_t* As = gsm + (it & 1) * G_BUF_WORDS;
        const uint32_t* Ws = As + 128 * 36;

#pragma unroll
        for (int ks = 0; ks < 4; ks++) {
            const int d = ks * 8 + q;
            uint32_t a[2][4];
#pragma unroll
            for (int mf = 0; mf < 2; mf++) {
                int row = wm * 32 + mf * 16 + g;
                a[mf][0] = As[row * 36 + d];
                a[mf][1] = As[(row + 8) * 36 + d];
                a[mf][2] = As[row * 36 + d + 4];
                a[mf][3] = As[(row + 8) * 36 + d + 4];
            }
#pragma unroll
            for (int nf = 0; nf < 8; nf++) {
                int n = wn * 64 + nf * 8 + g;
                uint32_t b0 = Ws[n * 36 + d];
                uint32_t b1 = Ws[n * 36 + d + 4];
                mma8(c[0][nf], a[0], b0, b1);
                mma8(c[1][nf], a[1], b0, b1);
            }
        }
        __syncthreads();
    }

#pragma unroll
    for (int mf = 0; mf < 2; mf++) {
#pragma unroll
        for (int nf = 0; nf < 8; nf++) {
            int col = n0 + wn * 64 + nf * 8 + 2 * q;
            float b0 = bias[col];
            float b1 = bias[col + 1];
#pragma unroll
            for (int half = 0; half < 2; half++) {
                int row = m0 + wm * 32 + mf * 16 + g + half * 8;
                float vx = c[mf][nf][half * 2 + 0] + b0;
                float vy = c[mf][nf][half * 2 + 1] + b1;
                float2 o;
                if (ROUND) {
                    o.x = __uint_as_float(f2tf(vx));
                    o.y = __uint_as_float(f2tf(vy));
                } else {
                    o.x = vx;
                    o.y = vy;
                }
                *(float2*)&C[(size_t)row * N + col] = o;
            }
        }
    }
}

// ---------------------------------------------------------------------------
// Fused differential attention, tf32 mma — branch-split across warps.
// Grid: (SEQ/64, BATCH*NHEADS). Block: 256 threads = 8 warps.
// Warp w: query-group qg = w>>1 (16 rows), branch br = w&1.
// Per-tile: each warp does 32 S-mmas + 32 exps + 64 AV-mmas (half of before)
// -> 16 warps/SM (vs 8), halved per-warp MUFU chain.
// K/V tiles (64x64, stride 72) double-buffered via cp.async.
// P buffers warp-private: [qg][br] 16x68.
// ---------------------------------------------------------------------------
#define KV_T 4608                           // words per 64x72 tile
#define AT_P  (4 * KV_T)                    // 18432: 8 bufs of 16*68
#define ATTN_SMEM_U32 (AT_P + 8 * 16 * 68)  // 27136
#define ATTN_SMEM_BYTES (ATTN_SMEM_U32 * 4) // 108544

__global__ __launch_bounds__(256, 2) void attn_tf32_kernel(
    const float* __restrict__ Qp, const float* __restrict__ Kp,
    const float* __restrict__ Vp,
    const float* __restrict__ lq1, const float* __restrict__ lk1,
    const float* __restrict__ lq2, const float* __restrict__ lk2,
    float* __restrict__ O)
{
    extern __shared__ uint32_t smu[];
    const uint32_t smem_base = (uint32_t)__cvta_generic_to_shared(smu);
    __shared__ float s_lam;

    const int tid  = threadIdx.x;
    const int lane = tid & 31;
    const int warp = tid >> 5;       // 0..7
    const int g = lane >> 2;         // 0..7
    const int q = lane & 3;          // 0..3
    const int qg = warp >> 1;        // 0..3 query group
    const int br = warp & 1;         // 0..1 branch
    const int qbase = qg * 16;

    const int t0 = blockIdx.x * 64;
    const int bh = blockIdx.y;
    const int b = bh >> 4;
    const int h = bh & 15;
    const size_t base = (size_t)b * SEQ * EMBED + (size_t)h * HD;

    // issue key/value tile into buffer buf (256 threads, 4 iters)
    auto issue_tile = [&](int tile, int buf) {
        const size_t rowbase = base + (size_t)(tile * 64) * EMBED;
#pragma unroll
        for (int i = 0; i < 4; i++) {
            int idx = tid + i * 256;   // 0..1023
            int row = idx >> 4;        // 0..63
            int dg  = idx & 15;        // 0..15
            uint32_t soff = (uint32_t)(buf * 2 * KV_T + row * 72 + dg * 4) * 4;
            cpasync16(smem_base + soff,
                      &Kp[rowbase + (size_t)row * EMBED + dg * 4]);
            cpasync16(smem_base + soff + KV_T * 4,
                      &Vp[rowbase + (size_t)row * EMBED + dg * 4]);
        }
        CP_COMMIT();
    };

    issue_tile(0, 0);

    // Warp 0: lambda scalar
    if (tid < 32) {
        float p1 = 0.f, p2 = 0.f;
        if (tid < SD) {
            p1 = lq1[tid] * lk1[tid];
            p2 = lq2[tid] * lk2[tid];
        }
#pragma unroll
        for (int m = 16; m >= 1; m >>= 1) {
            p1 += __shfl_xor_sync(0xffffffffu, p1, m);
            p2 += __shfl_xor_sync(0xffffffffu, p2, m);
        }
        if (tid == 0) s_lam = __expf(p1) - __expf(p2) + LAMBDA_INIT;
    }

    // Q A-fragments in registers, own branch only (values pre-rounded)
    uint32_t qa[4][4];
    {
        const float* qr0 = &Qp[base + (size_t)(t0 + qbase + g) * EMBED];
        const float* qr1 = &Qp[base + (size_t)(t0 + qbase + g + 8) * EMBED];
#pragma unroll
        for (int ks = 0; ks < 4; ks++) {
            int d = br * 32 + ks * 8 + q;
            qa[ks][0] = __float_as_uint(qr0[d]);
            qa[ks][1] = __float_as_uint(qr1[d]);
            qa[ks][2] = __float_as_uint(qr0[d + 4]);
            qa[ks][3] = __float_as_uint(qr1[d + 4]);
        }
    }

    float acc[8][4];
    float z[2];
#pragma unroll
    for (int nf = 0; nf < 8; nf++)
#pragma unroll
        for (int i = 0; i < 4; i++) acc[nf][i] = 0.f;
    z[0] = z[1] = 0.f;

    // Warp-private P buffer
    const uint32_t pbase = AT_P + (uint32_t)warp * (16 * 68);

    for (int it = 0; it < SEQ / 64; it++) {
        CP_WAIT0();
        __syncthreads();
        if (it + 1 < SEQ / 64) issue_tile(it + 1, (it + 1) & 1);

        const uint32_t* Ks = smu + (it & 1) * 2 * KV_T;
        const uint32_t* Vs = Ks + KV_T;

        // ---- S phase (own branch only) ----
        float s[8][4];
#pragma unroll
        for (int nf = 0; nf < 8; nf++)
#pragma unroll
            for (int i = 0; i < 4; i++) s[nf][i] = 0.f;

#pragma unroll
        for (int ks = 0; ks < 4; ks++) {
            const int d = br * 32 + ks * 8 + q;
#pragma unroll
            for (int nf = 0; nf < 8; nf++) {
                int key = nf * 8 + g;
                uint32_t b0 = Ks[key * 72 + d];
                uint32_t b1 = Ks[key * 72 + d + 4];
                mma8(s[nf], qa[ks], b0, b1);
            }
        }

        // exp -> tf32-rounded P + row sums (from rounded values)
        float rs0 = 0.f, rs1 = 0.f;
#pragma unroll
        for (int nf = 0; nf < 8; nf++) {
#pragma unroll
            for (int i = 0; i < 4; i++) {
                float e = __expf(s[nf][i] * SCALING);
                uint32_t u = f2tf(e);
                float er = __uint_as_float(u);
                if (i < 2) rs0 += er; else rs1 += er;
                int prow = g + (i >> 1) * 8;
                int pcol = nf * 8 + 2 * q + (i & 1);
                smu[pbase + prow * 68 + pcol] = u;
            }
        }
        rs0 += __shfl_xor_sync(0xffffffffu, rs0, 1);
        rs0 += __shfl_xor_sync(0xffffffffu, rs0, 2);
        rs1 += __shfl_xor_sync(0xffffffffu, rs1, 1);
        rs1 += __shfl_xor_sync(0xffffffffu, rs1, 2);
        z[0] += rs0;
        z[1] += rs1;

        __syncwarp();   // P writes visible within warp

        // ---- AV phase (own branch) ----
#pragma unroll
        for (int ks = 0; ks < 8; ks++) {
            const int key = ks * 8 + q;
            uint32_t aP[4];
            aP[0] = smu[pbase + g * 68 + key];
            aP[1] = smu[pbase + (g + 8) * 68 + key];
            aP[2] = smu[pbase + g * 68 + key + 4];
            aP[3] = smu[pbase + (g + 8) * 68 + key + 4];
#pragma unroll
            for (int nf = 0; nf < 8; nf++) {
                uint32_t b0 = Vs[key * 72 + nf * 8 + g];
                uint32_t b1 = Vs[(key + 4) * 72 + nf * 8 + g];
                mma8(acc[nf], aP, b0, b1);
            }
        }
        __syncwarp();   // P reads done before next tile's P writes (same warp)
    }

    // ---- Epilogue ----
    // Branch-1 warps stage (acc * i2) into their P buffer; branch-0 warps
    // combine: out = round_tf32( acc1*i1 - staged2 ).
    const float lam = s_lam;
    float iv[2];
#pragma unroll
    for (int half = 0; half < 2; half++) {
        float num = (br == 0) ? ONE_MINUS_LI : (ONE_MINUS_LI * lam);
        iv[half] = num / z[half];
    }

    if (br == 1) {
#pragma unroll
        for (int nf = 0; nf < 8; nf++) {
#pragma unroll
            for (int i = 0; i < 4; i++) {
                int prow = g + (i >> 1) * 8;
                int pcol = nf * 8 + 2 * q + (i & 1);
                float v = acc[nf][i] * iv[i >> 1];
                smu[pbase + prow * 68 + pcol] = __float_as_uint(v);
            }
        }
    }
    __syncthreads();

    if (br == 0) {
        const uint32_t p2b = AT_P + (uint32_t)(warp + 1) * (16 * 68);  // partner buffer
#pragma unroll
        for (int nf = 0; nf < 8; nf++) {
            int col = nf * 8 + 2 * q;
#pragma unroll
            for (int half = 0; half < 2; half++) {
                int prow = g + half * 8;
                int row = t0 + qbase + prow;
                float s2x = __uint_as_float(smu[p2b + prow * 68 + col]);
                float s2y = __uint_as_float(smu[p2b + prow * 68 + col + 1]);
                float vx = acc[nf][half * 2 + 0] * iv[half] - s2x;
                float vy = acc[nf][half * 2 + 1] * iv[half] - s2y;
                float2 o;
                o.x = __uint_as_float(f2tf(vx));
                o.y = __uint_as_float(f2tf(vy));
                *(float2*)&O[base + (size_t)row * EMBED + col] = o;
            }
        }
    }
}

// ---------------------------------------------------------------------------
// Host launch
// ---------------------------------------------------------------------------
extern "C" void kernel_launch(void* const* d_in, const int* in_sizes, int n_in,
                              void* d_out, int out_size)
{
    const float* query = (const float*)d_in[0];
    const float* key   = (const float*)d_in[1];
    const float* value = (const float*)d_in[2];
    const float* in_w  = (const float*)d_in[3];   // [3072][1024]
    const float* in_b  = (const float*)d_in[4];   // [3072]
    const float* out_w = (const float*)d_in[5];   // [1024][1024]
    const float* out_b = (const float*)d_in[6];   // [1024]
    const float* lq1   = (const float*)d_in[7];
    const float* lk1   = (const float*)d_in[8];
    const float* lq2   = (const float*)d_in[9];
    const float* lk2   = (const float*)d_in[10];
    float* out = (float*)d_out;

    float *qp, *kp, *vp, *op, *xq, *xk, *xv, *w1, *w2;
    cudaGetSymbolAddress((void**)&qp, g_Q);
    cudaGetSymbolAddress((void**)&kp, g_K);
    cudaGetSymbolAddress((void**)&vp, g_V);
    cudaGetSymbolAddress((void**)&op, g_O);
    cudaGetSymbolAddress((void**)&xq, g_xq);
    cudaGetSymbolAddress((void**)&xk, g_xk);
    cudaGetSymbolAddress((void**)&xv, g_xv);
    cudaGetSymbolAddress((void**)&w1, g_w1);
    cudaGetSymbolAddress((void**)&w2, g_w2);

    cudaFuncSetAttribute(attn_tf32_kernel,
                         cudaFuncAttributeMaxDynamicSharedMemorySize,
                         ATTN_SMEM_BYTES);
    cudaFuncSetAttribute(gemm_tf32_async<true>,
                         cudaFuncAttributeMaxDynamicSharedMemorySize,
                         G_SMEM_BYTES);
    cudaFuncSetAttribute(gemm_tf32_async<false>,
                         cudaFuncAttributeMaxDynamicSharedMemorySize,
                         G_SMEM_BYTES);

    // --- tf32 pre-rounding of all GEMM inputs ---
    const int n4_act = (MTOT * EMBED) / 4;          // 1048576
    round_tf32_kernel<<<1024, 256>>>((const float4*)query, (float4*)xq, n4_act);
    round_tf32_kernel<<<1024, 256>>>((const float4*)key,   (float4*)xk, n4_act);
    round_tf32_kernel<<<1024, 256>>>((const float4*)value, (float4*)xv, n4_act);
    round_tf32_kernel<<<1024, 256>>>((const float4*)in_w,  (float4*)w1, (3 * 1024 * 1024) / 4);
    round_tf32_kernel<<<1024, 256>>>((const float4*)out_w, (float4*)w2, (1024 * 1024) / 4);

    dim3 gblk(256);
    dim3 ggrid(EMBED / 128, MTOT / 128);   // (8, 32)

    // QKV projections (outputs tf32-rounded)
    gemm_tf32_async<true><<<ggrid, gblk, G_SMEM_BYTES>>>(xq, w1,                   in_b,        qp, MTOT, EMBED, EMBED);
    gemm_tf32_async<true><<<ggrid, gblk, G_SMEM_BYTES>>>(xk, w1 + 1024 * 1024,     in_b + 1024, kp, MTOT, EMBED, EMBED);
    gemm_tf32_async<true><<<ggrid, gblk, G_SMEM_BYTES>>>(xv, w1 + 2 * 1024 * 1024, in_b + 2048, vp, MTOT, EMBED, EMBED);

    // Fused differential attention (branch-split warps)
    dim3 agrid(SEQ / 64, BATCH * NHEADS);  // (32, 32)
    attn_tf32_kernel<<<agrid, 256, ATTN_SMEM_BYTES>>>(qp, kp, vp, lq1, lk1, lq2, lk2, op);

    // Output projection -> d_out (raw f32 output)
    gemm_tf32_async<false><<<ggrid, gblk, G_SMEM_BYTES>>>(op, w2, out_b, out, MTOT, EMBED, EMBED);
}

// round 11
// speedup vs baseline: 1.0637x; 1.0637x over previous
#include <cuda_runtime.h>
#include <math.h>
#include <stdint.h>

// Problem constants
#define EMBED   1024
#define BATCH   2
#define SEQ     2048
#define NHEADS  16
#define HD      64
#define SD      32
#define MTOT    (BATCH*SEQ)          // 4096
#define SCALING 0.17677669529663687f // 1/sqrt(32)
#define LAMBDA_INIT 0.2f             // 0.8 - 0.6*exp(0)
#define ONE_MINUS_LI 0.8f

// Scratch (device globals; no runtime allocation allowed)
__device__ float g_Q[(size_t)MTOT * EMBED];   // projected Q (tf32-rounded)
__device__ float g_K[(size_t)MTOT * EMBED];   // projected K (tf32-rounded)
__device__ float g_Vt[(size_t)MTOT * EMBED];  // projected V, d-major [b*16+h][64][2048]
__device__ float g_O[(size_t)MTOT * EMBED];   // attn out   (tf32-rounded)
__device__ float g_xq[(size_t)MTOT * EMBED];  // rounded input query
__device__ float g_xk[(size_t)MTOT * EMBED];  // rounded input key
__device__ float g_xv[(size_t)MTOT * EMBED];  // rounded input value
__device__ float g_w1[3 * 1024 * 1024];       // rounded in_proj_weight
__device__ float g_w2[1024 * 1024];           // rounded out_proj_weight

// ---------------------------------------------------------------------------
// tf32 + cp.async + ldmatrix helpers
// ---------------------------------------------------------------------------
__device__ __forceinline__ uint32_t f2tf(float x) {
    uint32_t r;
    asm("cvt.rna.tf32.f32 %0, %1;" : "=r"(r) : "f"(x));
    return r;
}
__device__ __forceinline__ uint4 cvt4(float4 v) {
    return make_uint4(f2tf(v.x), f2tf(v.y), f2tf(v.z), f2tf(v.w));
}
__device__ __forceinline__ void cpasync16(uint32_t smem_addr, const void* gptr) {
    asm volatile("cp.async.cg.shared.global [%0], [%1], 16;"
                 :: "r"(smem_addr), "l"(gptr));
}
#define CP_COMMIT() asm volatile("cp.async.commit_group;")
#define CP_WAIT0()  asm volatile("cp.async.wait_group 0;")

__device__ __forceinline__ void ldsm4(uint32_t& r0, uint32_t& r1,
                                      uint32_t& r2, uint32_t& r3, uint32_t addr) {
    asm volatile("ldmatrix.sync.aligned.m8n8.x4.shared.b16 {%0,%1,%2,%3}, [%4];"
                 : "=r"(r0), "=r"(r1), "=r"(r2), "=r"(r3) : "r"(addr));
}

// D += A(16x8) * B(8x8), tf32 inputs, f32 accumulate.
__device__ __forceinline__ void mma8(float* c, const uint32_t* a,
                                     uint32_t b0, uint32_t b1) {
    asm volatile(
        "mma.sync.aligned.m16n8k8.row.col.f32.tf32.tf32.f32 "
        "{%0,%1,%2,%3}, {%4,%5,%6,%7}, {%8,%9}, {%0,%1,%2,%3};"
        : "+f"(c[0]), "+f"(c[1]), "+f"(c[2]), "+f"(c[3])
        : "r"(a[0]), "r"(a[1]), "r"(a[2]), "r"(a[3]), "r"(b0), "r"(b1));
}

// ---------------------------------------------------------------------------
// Elementwise tf32 rounding pass (float4 grid-stride)
// ---------------------------------------------------------------------------
__global__ void round_tf32_kernel(const float4* __restrict__ in,
                                  float4* __restrict__ out, int n4)
{
    int i = blockIdx.x * blockDim.x + threadIdx.x;
    int stride = gridDim.x * blockDim.x;
    for (; i < n4; i += stride) {
        uint4 u = cvt4(in[i]);
        out[i] = *(float4*)&u;
    }
}

// ---------------------------------------------------------------------------
// tf32 GEMM (cp.async double-buffered): C = A[M,K] @ W[N,K]^T + bias
// MODE 0: plain f32 output.  MODE 1: tf32-rounded output.
// MODE 2: tf32-rounded output written TRANSPOSED per-head d-major into
//         Vt[(b*16+h)*64 + d][token]  (for the attention V operand).
// ---------------------------------------------------------------------------
#define G_BUF_WORDS (2 * 128 * 36)          // 9216 words per buffer
#define G_SMEM_BYTES (2 * G_BUF_WORDS * 4)  // 73728

template<int MODE>
__global__ __launch_bounds__(256, 2) void gemm_tf32_async(
    const float* __restrict__ A, const float* __restrict__ W,
    const float* __restrict__ bias, float* __restrict__ C,
    int M, int N, int K)
{
    extern __shared__ uint32_t gsm[];
    const uint32_t smem_base = (uint32_t)__cvta_generic_to_shared(gsm);

    const int tid  = threadIdx.x;
    const int lane = tid & 31;
    const int warp = tid >> 5;
    const int g = lane >> 2;
    const int q = lane & 3;
    const int wm = warp >> 1;      // 0..3
    const int wn = warp & 1;       // 0..1
    const int m0 = blockIdx.y * 128;
    const int n0 = blockIdx.x * 128;

    const int nchunks = K >> 5;    // K/32

    auto issue = [&](int ck, int buf) {
        const int k0 = ck * 32;
#pragma unroll
        for (int i = 0; i < 4; i++) {
            int idx = tid + i * 256;   // 0..1023
            int row = idx >> 3;        // 0..127
            int kg  = idx & 7;         // 0..7
            uint32_t soff = (uint32_t)(buf * G_BUF_WORDS + row * 36 + kg * 4) * 4;
            cpasync16(smem_base + soff,
                      &A[(size_t)(m0 + row) * K + k0 + kg * 4]);
            cpasync16(smem_base + soff + 128 * 36 * 4,
                      &W[(size_t)(n0 + row) * K + k0 + kg * 4]);
        }
        CP_COMMIT();
    };

    float c[2][8][4];
#pragma unroll
    for (int mf = 0; mf < 2; mf++)
#pragma unroll
        for (int nf = 0; nf < 8; nf++)
#pragma unroll
            for (int i = 0; i < 4; i++) c[mf][nf][i] = 0.f;

    issue(0, 0);

    for (int it = 0; it < nchunks; it++) {
        CP_WAIT0();
        __syncthreads();
        if (it + 1 < nchunks) issue(it + 1, (it + 1) & 1);

        const uint32_t* As = gsm + (it & 1) * G_BUF_WORDS;
        const uint32_t* Ws = As + 128 * 36;

#pragma unroll
        for (int ks = 0; ks < 4; ks++) {
            const int d = ks * 8 + q;
            uint32_t a[2][4];
#pragma unroll
            for (int mf = 0; mf < 2; mf++) {
                int row = wm * 32 + mf * 16 + g;
                a[mf][0] = As[row * 36 + d];
                a[mf][1] = As[(row + 8) * 36 + d];
                a[mf][2] = As[row * 36 + d + 4];
                a[mf][3] = As[(row + 8) * 36 + d + 4];
            }
#pragma unroll
            for (int nf = 0; nf < 8; nf++) {
                int n = wn * 64 + nf * 8 + g;
                uint32_t b0 = Ws[n * 36 + d];
                uint32_t b1 = Ws[n * 36 + d + 4];
                mma8(c[0][nf], a[0], b0, b1);
                mma8(c[1][nf], a[1], b0, b1);
            }
        }
        __syncthreads();
    }

#pragma unroll
    for (int mf = 0; mf < 2; mf++) {
#pragma unroll
        for (int nf = 0; nf < 8; nf++) {
            int col = n0 + wn * 64 + nf * 8 + 2 * q;
            float b0 = bias[col];
            float b1 = bias[col + 1];
#pragma unroll
            for (int half = 0; half < 2; half++) {
                int row = m0 + wm * 32 + mf * 16 + g + half * 8;
                float vx = c[mf][nf][half * 2 + 0] + b0;
                float vy = c[mf][nf][half * 2 + 1] + b1;
                if (MODE == 0) {
                    float2 o; o.x = vx; o.y = vy;
                    *(float2*)&C[(size_t)row * N + col] = o;
                } else if (MODE == 1) {
                    float2 o;
                    o.x = __uint_as_float(f2tf(vx));
                    o.y = __uint_as_float(f2tf(vy));
                    *(float2*)&C[(size_t)row * N + col] = o;
                } else {
                    // MODE 2: transposed per-head d-major write
                    int h  = col >> 6;        // head
                    int dd = col & 63;        // dim within head (dd, dd+1)
                    int bb = row >> 11;       // batch
                    int tok = row & 2047;
                    size_t vt = ((size_t)(bb * 16 + h) * 64 + dd) * SEQ + tok;
                    C[vt]        = __uint_as_float(f2tf(vx));
                    C[vt + SEQ]  = __uint_as_float(f2tf(vy));  // dd+1
                }
            }
        }
    }
}

// ---------------------------------------------------------------------------
// Fused differential attention, tf32 mma + ldmatrix operand loads.
// Grid: (SEQ/64, BATCH*NHEADS). Block: 128 threads = 4 warps; warp owns 16
// query rows, BOTH branches (V frags shared). K natural [key][d], V d-major
// [d][key] (from MODE-2 GEMM), P [qrow][key]; all smem strides 68 words
// (272B: 16B-aligned rows, conflict-free ldmatrix phases).
// K/V double-buffered via cp.async. P warp-private (syncwarp only).
// ---------------------------------------------------------------------------
#define KV_T 4352                            // words per 64x68 tile
#define AT_P (4 * KV_T)                      // 17408 (2 stages x K+Vt)
#define ATTN_SMEM_U32 (AT_P + 8 * 16 * 68)   // 26112
#define ATTN_SMEM_BYTES (ATTN_SMEM_U32 * 4)  // 104448

__global__ __launch_bounds__(128, 2) void attn_tf32_kernel(
    const float* __restrict__ Qp, const float* __restrict__ Kp,
    const float* __restrict__ Vt,
    const float* __restrict__ lq1, const float* __restrict__ lk1,
    const float* __restrict__ lq2, const float* __restrict__ lk2,
    float* __restrict__ O)
{
    extern __shared__ uint32_t smu[];
    const uint32_t smem_base = (uint32_t)__cvta_generic_to_shared(smu);
    __shared__ float s_lam;

    const int tid  = threadIdx.x;
    const int lane = tid & 31;
    const int warp = tid >> 5;       // 0..3
    const int g = lane >> 2;         // 0..7
    const int q = lane & 3;          // 0..3
    const int qbase = warp * 16;

    const int t0 = blockIdx.x * 64;
    const int bh = blockIdx.y;       // b*16 + h
    const int b = bh >> 4;
    const int h = bh & 15;
    const size_t base = (size_t)b * SEQ * EMBED + (size_t)h * HD;
    const size_t vtbase = (size_t)bh * 64 * SEQ;   // Vt[(bh)*64 + d][token]

    // issue K (natural) + Vt (d-major) tile into stage buf
    auto issue_tile = [&](int tile, int buf) {
        const int s0 = tile * 64;
        const size_t krow = base + (size_t)s0 * EMBED;
#pragma unroll
        for (int i = 0; i < 8; i++) {
            int idx = tid + i * 128;   // 0..1023
            int row = idx >> 4;        // 0..63
            int dg  = idx & 15;        // 0..15 (16B chunk)
            uint32_t soff = (uint32_t)(buf * 2 * KV_T + row * 68 + dg * 4) * 4;
            cpasync16(smem_base + soff,
                      &Kp[krow + (size_t)row * EMBED + dg * 4]);
            // Vt: row = d, chunk dg covers keys s0+dg*4..+3
            cpasync16(smem_base + soff + KV_T * 4,
                      &Vt[vtbase + (size_t)row * SEQ + s0 + dg * 4]);
        }
        CP_COMMIT();
    };

    issue_tile(0, 0);

    // Warp 0: lambda scalar
    if (tid < 32) {
        float p1 = 0.f, p2 = 0.f;
        if (tid < SD) {
            p1 = lq1[tid] * lk1[tid];
            p2 = lq2[tid] * lk2[tid];
        }
#pragma unroll
        for (int m = 16; m >= 1; m >>= 1) {
            p1 += __shfl_xor_sync(0xffffffffu, p1, m);
            p2 += __shfl_xor_sync(0xffffffffu, p2, m);
        }
        if (tid == 0) s_lam = __expf(p1) - __expf(p2) + LAMBDA_INIT;
    }

    // Q A-fragments in registers (values pre-rounded tf32)
    uint32_t qa[2][4][4];
    {
        const float* qr0 = &Qp[base + (size_t)(t0 + qbase + g) * EMBED];
        const float* qr1 = &Qp[base + (size_t)(t0 + qbase + g + 8) * EMBED];
#pragma unroll
        for (int br = 0; br < 2; br++)
#pragma unroll
            for (int ks = 0; ks < 4; ks++) {
                int d = br * 32 + ks * 8 + q;
                qa[br][ks][0] = __float_as_uint(qr0[d]);
                qa[br][ks][1] = __float_as_uint(qr1[d]);
                qa[br][ks][2] = __float_as_uint(qr0[d + 4]);
                qa[br][ks][3] = __float_as_uint(qr1[d + 4]);
            }
    }

    float acc1[8][4], acc2[8][4];
    float z[2][2];
#pragma unroll
    for (int nf = 0; nf < 8; nf++)
#pragma unroll
        for (int i = 0; i < 4; i++) { acc1[nf][i] = 0.f; acc2[nf][i] = 0.f; }
    z[0][0] = z[0][1] = z[1][0] = z[1][1] = 0.f;

    // ldmatrix per-thread offsets (bytes)
    const int lm7 = lane & 7;
    const int lb3 = (lane >> 3) & 1;
    const int lb4 = lane >> 4;
    // K / Vt B-frags: m0/m1 = rows r0..r0+7 cols +0/+4; m2/m3 = rows +8
    const uint32_t kv_off = (uint32_t)((lm7 + 8 * lb4) * 68 + 4 * lb3) * 4;
    // P A-frags: m0/m1 = rows 0-7 / 8-15 col k0; m2/m3 = col k0+4
    const uint32_t pa_off = (uint32_t)((lm7 + 8 * lb3) * 68 + 4 * lb4) * 4;

    // P buffers (warp-private, per branch), word offsets
    const uint32_t p1w = AT_P + (uint32_t)(warp * 2 + 0) * (16 * 68);
    const uint32_t p2w = AT_P + (uint32_t)(warp * 2 + 1) * (16 * 68);
    const uint32_t p1addr = smem_base + p1w * 4 + pa_off;
    const uint32_t p2addr = smem_base + p2w * 4 + pa_off;

    for (int it = 0; it < SEQ / 64; it++) {
        CP_WAIT0();
        __syncthreads();
        if (it + 1 < SEQ / 64) issue_tile(it + 1, (it + 1) & 1);

        const uint32_t kaddr = smem_base + (uint32_t)((it & 1) * 2 * KV_T) * 4 + kv_off;
        const uint32_t vaddr = kaddr + (uint32_t)KV_T * 4;

        // ---- S phase: one branch at a time ----
#pragma unroll
        for (int br = 0; br < 2; br++) {
            const uint32_t pbw = br ? p2w : p1w;

            float s[8][4];
#pragma unroll
            for (int nf = 0; nf < 8; nf++)
#pragma unroll
                for (int i = 0; i < 4; i++) s[nf][i] = 0.f;

#pragma unroll
            for (int ks = 0; ks < 4; ks++) {
                const uint32_t dcol = (uint32_t)(br * 32 + ks * 8) * 4;
#pragma unroll
                for (int nfp = 0; nfp < 4; nfp++) {
                    uint32_t r0, r1, r2, r3;
                    ldsm4(r0, r1, r2, r3,
                          kaddr + (uint32_t)(nfp * 16 * 68) * 4 + dcol);
                    mma8(s[2 * nfp + 0], qa[br][ks], r0, r1);
                    mma8(s[2 * nfp + 1], qa[br][ks], r2, r3);
                }
            }

            // exp -> tf32-rounded P (STS.64) + row sums from rounded values
            float rs0 = 0.f, rs1 = 0.f;
#pragma unroll
            for (int nf = 0; nf < 8; nf++) {
                uint32_t u0 = f2tf(__expf(s[nf][0] * SCALING));
                uint32_t u1 = f2tf(__expf(s[nf][1] * SCALING));
                uint32_t u2 = f2tf(__expf(s[nf][2] * SCALING));
                uint32_t u3 = f2tf(__expf(s[nf][3] * SCALING));
                rs0 += __uint_as_float(u0) + __uint_as_float(u1);
                rs1 += __uint_as_float(u2) + __uint_as_float(u3);
                *(uint2*)&smu[pbw + (g)     * 68 + nf * 8 + 2 * q] = make_uint2(u0, u1);
                *(uint2*)&smu[pbw + (g + 8) * 68 + nf * 8 + 2 * q] = make_uint2(u2, u3);
            }
            rs0 += __shfl_xor_sync(0xffffffffu, rs0, 1);
            rs0 += __shfl_xor_sync(0xffffffffu, rs0, 2);
            rs1 += __shfl_xor_sync(0xffffffffu, rs1, 1);
            rs1 += __shfl_xor_sync(0xffffffffu, rs1, 2);
            z[br][0] += rs0;
            z[br][1] += rs1;
        }
        __syncwarp();   // P writes visible within warp

        // ---- AV phase: both branches share V fragments ----
#pragma unroll
        for (int ks = 0; ks < 8; ks++) {
            const uint32_t kcol = (uint32_t)(ks * 8) * 4;
            uint32_t aP1[4], aP2[4];
            ldsm4(aP1[0], aP1[1], aP1[2], aP1[3], p1addr + kcol);
            ldsm4(aP2[0], aP2[1], aP2[2], aP2[3], p2addr + kcol);
#pragma unroll
            for (int nfp = 0; nfp < 4; nfp++) {
                uint32_t v0, v1, v2, v3;
                ldsm4(v0, v1, v2, v3,
                      vaddr + (uint32_t)(nfp * 16 * 68) * 4 + kcol);
                mma8(acc1[2 * nfp + 0], aP1, v0, v1);
                mma8(acc1[2 * nfp + 1], aP1, v2, v3);
                mma8(acc2[2 * nfp + 0], aP2, v0, v1);
                mma8(acc2[2 * nfp + 1], aP2, v2, v3);
            }
        }
        __syncwarp();   // P reads done before next tile's P writes (same warp)
    }

    // Epilogue: out = round_tf32( 0.8*(acc1/Z1 - lam*acc2/Z2) )
    const float lam = s_lam;
    float i1[2], i2[2];
#pragma unroll
    for (int half = 0; half < 2; half++) {
        i1[half] = ONE_MINUS_LI / z[0][half];
        i2[half] = ONE_MINUS_LI * lam / z[1][half];
    }
#pragma unroll
    for (int nf = 0; nf < 8; nf++) {
        int col = nf * 8 + 2 * q;
#pragma unroll
        for (int half = 0; half < 2; half++) {
            int row = t0 + qbase + g + half * 8;
            float vx = acc1[nf][half * 2 + 0] * i1[half] - acc2[nf][half * 2 + 0] * i2[half];
            float vy = acc1[nf][half * 2 + 1] * i1[half] - acc2[nf][half * 2 + 1] * i2[half];
            float2 o;
            o.x = __uint_as_float(f2tf(vx));
            o.y = __uint_as_float(f2tf(vy));
            *(float2*)&O[base + (size_t)row * EMBED + col] = o;
        }
    }
}

// ---------------------------------------------------------------------------
// Host launch
// ---------------------------------------------------------------------------
extern "C" void kernel_launch(void* const* d_in, const int* in_sizes, int n_in,
                              void* d_out, int out_size)
{
    const float* query = (const float*)d_in[0];
    const float* key   = (const float*)d_in[1];
    const float* value = (const float*)d_in[2];
    const float* in_w  = (const float*)d_in[3];   // [3072][1024]
    const float* in_b  = (const float*)d_in[4];   // [3072]
    const float* out_w = (const float*)d_in[5];   // [1024][1024]
    const float* out_b = (const float*)d_in[6];   // [1024]
    const float* lq1   = (const float*)d_in[7];
    const float* lk1   = (const float*)d_in[8];
    const float* lq2   = (const float*)d_in[9];
    const float* lk2   = (const float*)d_in[10];
    float* out = (float*)d_out;

    float *qp, *kp, *vt, *op, *xq, *xk, *xv, *w1, *w2;
    cudaGetSymbolAddress((void**)&qp, g_Q);
    cudaGetSymbolAddress((void**)&kp, g_K);
    cudaGetSymbolAddress((void**)&vt, g_Vt);
    cudaGetSymbolAddress((void**)&op, g_O);
    cudaGetSymbolAddress((void**)&xq, g_xq);
    cudaGetSymbolAddress((void**)&xk, g_xk);
    cudaGetSymbolAddress((void**)&xv, g_xv);
    cudaGetSymbolAddress((void**)&w1, g_w1);
    cudaGetSymbolAddress((void**)&w2, g_w2);

    cudaFuncSetAttribute(attn_tf32_kernel,
                         cudaFuncAttributeMaxDynamicSharedMemorySize,
                         ATTN_SMEM_BYTES);
    cudaFuncSetAttribute(gemm_tf32_async<0>,
                         cudaFuncAttributeMaxDynamicSharedMemorySize, G_SMEM_BYTES);
    cudaFuncSetAttribute(gemm_tf32_async<1>,
                         cudaFuncAttributeMaxDynamicSharedMemorySize, G_SMEM_BYTES);
    cudaFuncSetAttribute(gemm_tf32_async<2>,
                         cudaFuncAttributeMaxDynamicSharedMemorySize, G_SMEM_BYTES);

    // --- tf32 pre-rounding of all GEMM inputs ---
    const int n4_act = (MTOT * EMBED) / 4;          // 1048576
    round_tf32_kernel<<<1024, 256>>>((const float4*)query, (float4*)xq, n4_act);
    round_tf32_kernel<<<1024, 256>>>((const float4*)key,   (float4*)xk, n4_act);
    round_tf32_kernel<<<1024, 256>>>((const float4*)value, (float4*)xv, n4_act);
    round_tf32_kernel<<<1024, 256>>>((const float4*)in_w,  (float4*)w1, (3 * 1024 * 1024) / 4);
    round_tf32_kernel<<<1024, 256>>>((const float4*)out_w, (float4*)w2, (1024 * 1024) / 4);

    dim3 gblk(256);
    dim3 ggrid(EMBED / 128, MTOT / 128);   // (8, 32)

    // QKV projections (Q/K tf32-rounded natural; V tf32-rounded transposed)
    gemm_tf32_async<1><<<ggrid, gblk, G_SMEM_BYTES>>>(xq, w1,                   in_b,        qp, MTOT, EMBED, EMBED);
    gemm_tf32_async<1><<<ggrid, gblk, G_SMEM_BYTES>>>(xk, w1 + 1024 * 1024,     in_b + 1024, kp, MTOT, EMBED, EMBED);
    gemm_tf32_async<2><<<ggrid, gblk, G_SMEM_BYTES>>>(xv, w1 + 2 * 1024 * 1024, in_b + 2048, vt, MTOT, EMBED, EMBED);

    // Fused differential attention (ldmatrix operand loads)
    dim3 agrid(SEQ / 64, BATCH * NHEADS);  // (32, 32)
    attn_tf32_kernel<<<agrid, 128, ATTN_SMEM_BYTES>>>(qp, kp, vt, lq1, lk1, lq2, lk2, op);

    // Output projection -> d_out (raw f32 output)
    gemm_tf32_async<0><<<ggrid, gblk, G_SMEM_BYTES>>>(op, w2, out_b, out, MTOT, EMBED, EMBED);
}

// round 14
// speedup vs baseline: 1.0923x; 1.0268x over previous
#include <cuda_runtime.h>
#include <math.h>
#include <stdint.h>

// Problem constants
#define EMBED   1024
#define BATCH   2
#define SEQ     2048
#define NHEADS  16
#define HD      64
#define SD      32
#define MTOT    (BATCH*SEQ)          // 4096
#define SCALING 0.17677669529663687f // 1/sqrt(32)
#define EXP2C   0.25503483f          // SCALING * log2(e)
#define LAMBDA_INIT 0.2f             // 0.8 - 0.6*exp(0)
#define ONE_MINUS_LI 0.8f

// Scratch (device globals; no runtime allocation allowed)
__device__ float g_Q[(size_t)MTOT * EMBED];   // projected Q (tf32-rounded)
__device__ float g_K[(size_t)MTOT * EMBED];   // projected K (tf32-rounded)
__device__ float g_Vt[(size_t)MTOT * EMBED];  // projected V, d-major [b*16+h][64][2048]
__device__ float g_O[(size_t)MTOT * EMBED];   // attn out   (tf32-rounded)
__device__ float g_xq[(size_t)MTOT * EMBED];  // rounded input query
__device__ float g_xk[(size_t)MTOT * EMBED];  // rounded input key
__device__ float g_xv[(size_t)MTOT * EMBED];  // rounded input value
__device__ float g_w1[3 * 1024 * 1024];       // rounded in_proj_weight
__device__ float g_w2[1024 * 1024];           // rounded out_proj_weight

// ---------------------------------------------------------------------------
// tf32 + cp.async + ldmatrix helpers
// ---------------------------------------------------------------------------
__device__ __forceinline__ uint32_t f2tf(float x) {
    uint32_t r;
    asm("cvt.rna.tf32.f32 %0, %1;" : "=r"(r) : "f"(x));
    return r;
}
__device__ __forceinline__ uint4 cvt4(float4 v) {
    return make_uint4(f2tf(v.x), f2tf(v.y), f2tf(v.z), f2tf(v.w));
}
__device__ __forceinline__ float ex2(float x) {
    float r;
    asm("ex2.approx.f32 %0, %1;" : "=f"(r) : "f"(x));
    return r;
}
__device__ __forceinline__ void cpasync16(uint32_t smem_addr, const void* gptr) {
    asm volatile("cp.async.cg.shared.global [%0], [%1], 16;"
                 :: "r"(smem_addr), "l"(gptr));
}
#define CP_COMMIT() asm volatile("cp.async.commit_group;")
#define CP_WAIT0()  asm volatile("cp.async.wait_group 0;")
#define CP_WAIT1()  asm volatile("cp.async.wait_group 1;")

__device__ __forceinline__ void ldsm4(uint32_t& r0, uint32_t& r1,
                                      uint32_t& r2, uint32_t& r3, uint32_t addr) {
    asm volatile("ldmatrix.sync.aligned.m8n8.x4.shared.b16 {%0,%1,%2,%3}, [%4];"
                 : "=r"(r0), "=r"(r1), "=r"(r2), "=r"(r3) : "r"(addr));
}

// D += A(16x8) * B(8x8), tf32 inputs, f32 accumulate.
__device__ __forceinline__ void mma8(float* c, const uint32_t* a,
                                     uint32_t b0, uint32_t b1) {
    asm volatile(
        "mma.sync.aligned.m16n8k8.row.col.f32.tf32.tf32.f32 "
        "{%0,%1,%2,%3}, {%4,%5,%6,%7}, {%8,%9}, {%0,%1,%2,%3};"
        : "+f"(c[0]), "+f"(c[1]), "+f"(c[2]), "+f"(c[3])
        : "r"(a[0]), "r"(a[1]), "r"(a[2]), "r"(a[3]), "r"(b0), "r"(b1));
}

// ---------------------------------------------------------------------------
// Elementwise tf32 rounding pass (float4 grid-stride)
// ---------------------------------------------------------------------------
__global__ void round_tf32_kernel(const float4* __restrict__ in,
                                  float4* __restrict__ out, int n4)
{
    int i = blockIdx.x * blockDim.x + threadIdx.x;
    int stride = gridDim.x * blockDim.x;
    for (; i < n4; i += stride) {
        uint4 u = cvt4(in[i]);
        out[i] = *(float4*)&u;
    }
}

// ---------------------------------------------------------------------------
// tf32 GEMM, 3-stage cp.async pipeline + ldmatrix fragments.
// C = A[M,K] @ W[N,K]^T + bias. Inputs pre-rounded tf32.
// 128x128 tile, k-chunk 32, 256 threads = 8 warps (4m x 2n),
// warp tile 32x64 = 2 mf x 8 nf. Stride 36 words (144B: conflict-free ldsm).
// MODE 0: f32 out. MODE 1: tf32-rounded out. MODE 2: tf32-rounded transposed
//         per-head d-major out into Vt[(b*16+h)*64+d][token].
// ---------------------------------------------------------------------------
#define G_BUF_WORDS (2 * 128 * 36)          // 9216 words per stage (A+W)
#define G_STAGES 3
#define G_SMEM_BYTES (G_STAGES * G_BUF_WORDS * 4)  // 110592

template<int MODE>
__global__ __launch_bounds__(256, 2) void gemm_tf32_async(
    const float* __restrict__ A, const float* __restrict__ W,
    const float* __restrict__ bias, float* __restrict__ C,
    int M, int N, int K)
{
    extern __shared__ uint32_t gsm[];
    const uint32_t smem_base = (uint32_t)__cvta_generic_to_shared(gsm);

    const int tid  = threadIdx.x;
    const int lane = tid & 31;
    const int warp = tid >> 5;
    const int g = lane >> 2;
    const int q = lane & 3;
    const int wm = warp >> 1;      // 0..3
    const int wn = warp & 1;       // 0..1
    const int m0 = blockIdx.y * 128;
    const int n0 = blockIdx.x * 128;

    const int nchunks = K >> 5;    // K/32

    // issue chunk ck into stage buf; empty commit past the end (keeps
    // group numbering uniform so wait_group 1 drains correctly).
    auto issue = [&](int ck, int buf) {
        if (ck < nchunks) {
            const int k0 = ck * 32;
#pragma unroll
            for (int i = 0; i < 4; i++) {
                int idx = tid + i * 256;   // 0..1023
                int row = idx >> 3;        // 0..127
                int kg  = idx & 7;         // 0..7
                uint32_t soff = (uint32_t)(buf * G_BUF_WORDS + row * 36 + kg * 4) * 4;
                cpasync16(smem_base + soff,
                          &A[(size_t)(m0 + row) * K + k0 + kg * 4]);
                cpasync16(smem_base + soff + 128 * 36 * 4,
                          &W[(size_t)(n0 + row) * K + k0 + kg * 4]);
            }
        }
        CP_COMMIT();
    };

    float c[2][8][4];
#pragma unroll
    for (int mf = 0; mf < 2; mf++)
#pragma unroll
        for (int nf = 0; nf < 8; nf++)
#pragma unroll
            for (int i = 0; i < 4; i++) c[mf][nf][i] = 0.f;

    // ldmatrix per-thread offsets (bytes)
    const int lm7 = lane & 7;
    const int lb3 = (lane >> 3) & 1;
    const int lb4 = lane >> 4;
    // A-frag (per mf, per ks): m0/m1 rows 0-7/8-15 col k, m2/m3 cols k+4
    const uint32_t a_off = (uint32_t)((wm * 32 + lm7 + 8 * lb3) * 36 + 4 * lb4) * 4;
    // B-frag (per nf-pair, per ks): m0/m1 rows n..n+7 cols k/k+4, m2/m3 rows +8
    const uint32_t b_off = (uint32_t)((128 + wn * 64 + lm7 + 8 * lb4) * 36 + 4 * lb3) * 4;

    issue(0, 0);
    issue(1, 1);

    for (int it = 0; it < nchunks; it++) {
        CP_WAIT1();                 // group(it) complete (group it+1 may fly)
        __syncthreads();            // all warps done with stage (it+2)%3
        issue(it + 2, (it + 2) % G_STAGES);

        const uint32_t stage = smem_base + (uint32_t)((it % G_STAGES) * G_BUF_WORDS) * 4;

#pragma unroll
        for (int ks = 0; ks < 4; ks++) {
            const uint32_t kcol = (uint32_t)(ks * 8) * 4;
            uint32_t a[2][4];
#pragma unroll
            for (int mf = 0; mf < 2; mf++)
                ldsm4(a[mf][0], a[mf][1], a[mf][2], a[mf][3],
                      stage + a_off + (uint32_t)(mf * 16 * 36) * 4 + kcol);
#pragma unroll
            for (int np = 0; np < 4; np++) {
                uint32_t b0, b1, b2, b3;
                ldsm4(b0, b1, b2, b3,
                      stage + b_off + (uint32_t)(np * 16 * 36) * 4 + kcol);
                mma8(c[0][2 * np + 0], a[0], b0, b1);
                mma8(c[1][2 * np + 0], a[1], b0, b1);
                mma8(c[0][2 * np + 1], a[0], b2, b3);
                mma8(c[1][2 * np + 1], a[1], b2, b3);
            }
        }
    }

#pragma unroll
    for (int mf = 0; mf < 2; mf++) {
#pragma unroll
        for (int nf = 0; nf < 8; nf++) {
            int col = n0 + wn * 64 + nf * 8 + 2 * q;
            float b0 = bias[col];
            float b1 = bias[col + 1];
#pragma unroll
            for (int half = 0; half < 2; half++) {
                int row = m0 + wm * 32 + mf * 16 + g + half * 8;
                float vx = c[mf][nf][half * 2 + 0] + b0;
                float vy = c[mf][nf][half * 2 + 1] + b1;
                if (MODE == 0) {
                    float2 o; o.x = vx; o.y = vy;
                    *(float2*)&C[(size_t)row * N + col] = o;
                } else if (MODE == 1) {
                    float2 o;
                    o.x = __uint_as_float(f2tf(vx));
                    o.y = __uint_as_float(f2tf(vy));
                    *(float2*)&C[(size_t)row * N + col] = o;
                } else {
                    int h  = col >> 6;        // head
                    int dd = col & 63;        // dim within head (dd, dd+1)
                    int bb = row >> 11;       // batch
                    int tok = row & 2047;
                    size_t vt = ((size_t)(bb * 16 + h) * 64 + dd) * SEQ + tok;
                    C[vt]       = __uint_as_float(f2tf(vx));
                    C[vt + SEQ] = __uint_as_float(f2tf(vy));  // dd+1
                }
            }
        }
    }
}

// ---------------------------------------------------------------------------
// Fused differential attention, tf32 mma + ldmatrix operand loads.
// (structure unchanged from R11; exp via single-FMUL ex2.approx)
// ---------------------------------------------------------------------------
#define KV_T 4352                            // words per 64x68 tile
#define AT_P (4 * KV_T)                      // 17408 (2 stages x K+Vt)
#define ATTN_SMEM_U32 (AT_P + 8 * 16 * 68)   // 26112
#define ATTN_SMEM_BYTES (ATTN_SMEM_U32 * 4)  // 104448

__global__ __launch_bounds__(128, 2) void attn_tf32_kernel(
    const float* __restrict__ Qp, const float* __restrict__ Kp,
    const float* __restrict__ Vt,
    const float* __restrict__ lq1, const float* __restrict__ lk1,
    const float* __restrict__ lq2, const float* __restrict__ lk2,
    float* __restrict__ O)
{
    extern __shared__ uint32_t smu[];
    const uint32_t smem_base = (uint32_t)__cvta_generic_to_shared(smu);
    __shared__ float s_lam;

    const int tid  = threadIdx.x;
    const int lane = tid & 31;
    const int warp = tid >> 5;       // 0..3
    const int g = lane >> 2;         // 0..7
    const int q = lane & 3;          // 0..3
    const int qbase = warp * 16;

    const int t0 = blockIdx.x * 64;
    const int bh = blockIdx.y;       // b*16 + h
    const int b = bh >> 4;
    const int h = bh & 15;
    const size_t base = (size_t)b * SEQ * EMBED + (size_t)h * HD;
    const size_t vtbase = (size_t)bh * 64 * SEQ;   // Vt[(bh)*64 + d][token]

    // issue K (natural) + Vt (d-major) tile into stage buf
    auto issue_tile = [&](int tile, int buf) {
        const int s0 = tile * 64;
        const size_t krow = base + (size_t)s0 * EMBED;
#pragma unroll
        for (int i = 0; i < 8; i++) {
            int idx = tid + i * 128;   // 0..1023
            int row = idx >> 4;        // 0..63
            int dg  = idx & 15;        // 0..15 (16B chunk)
            uint32_t soff = (uint32_t)(buf * 2 * KV_T + row * 68 + dg * 4) * 4;
            cpasync16(smem_base + soff,
                      &Kp[krow + (size_t)row * EMBED + dg * 4]);
            cpasync16(smem_base + soff + KV_T * 4,
                      &Vt[vtbase + (size_t)row * SEQ + s0 + dg * 4]);
        }
        CP_COMMIT();
    };

    issue_tile(0, 0);

    // Warp 0: lambda scalar
    if (tid < 32) {
        float p1 = 0.f, p2 = 0.f;
        if (tid < SD) {
            p1 = lq1[tid] * lk1[tid];
            p2 = lq2[tid] * lk2[tid];
        }
#pragma unroll
        for (int m = 16; m >= 1; m >>= 1) {
            p1 += __shfl_xor_sync(0xffffffffu, p1, m);
            p2 += __shfl_xor_sync(0xffffffffu, p2, m);
        }
        if (tid == 0) s_lam = __expf(p1) - __expf(p2) + LAMBDA_INIT;
    }

    // Q A-fragments in registers (values pre-rounded tf32)
    uint32_t qa[2][4][4];
    {
        const float* qr0 = &Qp[base + (size_t)(t0 + qbase + g) * EMBED];
        const float* qr1 = &Qp[base + (size_t)(t0 + qbase + g + 8) * EMBED];
#pragma unroll
        for (int br = 0; br < 2; br++)
#pragma unroll
            for (int ks = 0; ks < 4; ks++) {
                int d = br * 32 + ks * 8 + q;
                qa[br][ks][0] = __float_as_uint(qr0[d]);
                qa[br][ks][1] = __float_as_uint(qr1[d]);
                qa[br][ks][2] = __float_as_uint(qr0[d + 4]);
                qa[br][ks][3] = __float_as_uint(qr1[d + 4]);
            }
    }

    float acc1[8][4], acc2[8][4];
    float z[2][2];
#pragma unroll
    for (int nf = 0; nf < 8; nf++)
#pragma unroll
        for (int i = 0; i < 4; i++) { acc1[nf][i] = 0.f; acc2[nf][i] = 0.f; }
    z[0][0] = z[0][1] = z[1][0] = z[1][1] = 0.f;

    // ldmatrix per-thread offsets (bytes)
    const int lm7 = lane & 7;
    const int lb3 = (lane >> 3) & 1;
    const int lb4 = lane >> 4;
    const uint32_t kv_off = (uint32_t)((lm7 + 8 * lb4) * 68 + 4 * lb3) * 4;
    const uint32_t pa_off = (uint32_t)((lm7 + 8 * lb3) * 68 + 4 * lb4) * 4;

    const uint32_t p1w = AT_P + (uint32_t)(warp * 2 + 0) * (16 * 68);
    const uint32_t p2w = AT_P + (uint32_t)(warp * 2 + 1) * (16 * 68);
    const uint32_t p1addr = smem_base + p1w * 4 + pa_off;
    const uint32_t p2addr = smem_base + p2w * 4 + pa_off;

    for (int it = 0; it < SEQ / 64; it++) {
        CP_WAIT0();
        __syncthreads();
        if (it + 1 < SEQ / 64) issue_tile(it + 1, (it + 1) & 1);

        const uint32_t kaddr = smem_base + (uint32_t)((it & 1) * 2 * KV_T) * 4 + kv_off;
        const uint32_t vaddr = kaddr + (uint32_t)KV_T * 4;

        // ---- S phase: one branch at a time ----
#pragma unroll
        for (int br = 0; br < 2; br++) {
            const uint32_t pbw = br ? p2w : p1w;

            float s[8][4];
#pragma unroll
            for (int nf = 0; nf < 8; nf++)
#pragma unroll
                for (int i = 0; i < 4; i++) s[nf][i] = 0.f;

#pragma unroll
            for (int ks = 0; ks < 4; ks++) {
                const uint32_t dcol = (uint32_t)(br * 32 + ks * 8) * 4;
#pragma unroll
                for (int nfp = 0; nfp < 4; nfp++) {
                    uint32_t r0, r1, r2, r3;
                    ldsm4(r0, r1, r2, r3,
                          kaddr + (uint32_t)(nfp * 16 * 68) * 4 + dcol);
                    mma8(s[2 * nfp + 0], qa[br][ks], r0, r1);
                    mma8(s[2 * nfp + 1], qa[br][ks], r2, r3);
                }
            }

            // exp2 -> tf32-rounded P (STS.64) + row sums from rounded values
            float rs0 = 0.f, rs1 = 0.f;
#pragma unroll
            for (int nf = 0; nf < 8; nf++) {
                uint32_t u0 = f2tf(ex2(s[nf][0] * EXP2C));
                uint32_t u1 = f2tf(ex2(s[nf][1] * EXP2C));
                uint32_t u2 = f2tf(ex2(s[nf][2] * EXP2C));
                uint32_t u3 = f2tf(ex2(s[nf][3] * EXP2C));
                rs0 += __uint_as_float(u0) + __uint_as_float(u1);
                rs1 += __uint_as_float(u2) + __uint_as_float(u3);
                *(uint2*)&smu[pbw + (g)     * 68 + nf * 8 + 2 * q] = make_uint2(u0, u1);
                *(uint2*)&smu[pbw + (g + 8) * 68 + nf * 8 + 2 * q] = make_uint2(u2, u3);
            }
            rs0 += __shfl_xor_sync(0xffffffffu, rs0, 1);
            rs0 += __shfl_xor_sync(0xffffffffu, rs0, 2);
            rs1 += __shfl_xor_sync(0xffffffffu, rs1, 1);
            rs1 += __shfl_xor_sync(0xffffffffu, rs1, 2);
            z[br][0] += rs0;
            z[br][1] += rs1;
        }
        __syncwarp();   // P writes visible within warp

        // ---- AV phase: both branches share V fragments ----
#pragma unroll
        for (int ks = 0; ks < 8; ks++) {
            const uint32_t kcol = (uint32_t)(ks * 8) * 4;
            uint32_t aP1[4], aP2[4];
            ldsm4(aP1[0], aP1[1], aP1[2], aP1[3], p1addr + kcol);
            ldsm4(aP2[0], aP2[1], aP2[2], aP2[3], p2addr + kcol);
#pragma unroll
            for (int nfp = 0; nfp < 4; nfp++) {
                uint32_t v0, v1, v2, v3;
                ldsm4(v0, v1, v2, v3,
                      vaddr + (uint32_t)(nfp * 16 * 68) * 4 + kcol);
                mma8(acc1[2 * nfp + 0], aP1, v0, v1);
                mma8(acc1[2 * nfp + 1], aP1, v2, v3);
                mma8(acc2[2 * nfp + 0], aP2, v0, v1);
                mma8(acc2[2 * nfp + 1], aP2, v2, v3);
            }
        }
        __syncwarp();   // P reads done before next tile's P writes (same warp)
    }

    // Epilogue: out = round_tf32( 0.8*(acc1/Z1 - lam*acc2/Z2) )
    const float lam = s_lam;
    float i1[2], i2[2];
#pragma unroll
    for (int half = 0; half < 2; half++) {
        i1[half] = ONE_MINUS_LI / z[0][half];
        i2[half] = ONE_MINUS_LI * lam / z[1][half];
    }
#pragma unroll
    for (int nf = 0; nf < 8; nf++) {
        int col = nf * 8 + 2 * q;
#pragma unroll
        for (int half = 0; half < 2; half++) {
            int row = t0 + qbase + g + half * 8;
            float vx = acc1[nf][half * 2 + 0] * i1[half] - acc2[nf][half * 2 + 0] * i2[half];
            float vy = acc1[nf][half * 2 + 1] * i1[half] - acc2[nf][half * 2 + 1] * i2[half];
            float2 o;
            o.x = __uint_as_float(f2tf(vx));
            o.y = __uint_as_float(f2tf(vy));
            *(float2*)&O[base + (size_t)row * EMBED + col] = o;
        }
    }
}

// ---------------------------------------------------------------------------
// Host launch
// ---------------------------------------------------------------------------
extern "C" void kernel_launch(void* const* d_in, const int* in_sizes, int n_in,
                              void* d_out, int out_size)
{
    const float* query = (const float*)d_in[0];
    const float* key   = (const float*)d_in[1];
    const float* value = (const float*)d_in[2];
    const float* in_w  = (const float*)d_in[3];   // [3072][1024]
    const float* in_b  = (const float*)d_in[4];   // [3072]
    const float* out_w = (const float*)d_in[5];   // [1024][1024]
    const float* out_b = (const float*)d_in[6];   // [1024]
    const float* lq1   = (const float*)d_in[7];
    const float* lk1   = (const float*)d_in[8];
    const float* lq2   = (const float*)d_in[9];
    const float* lk2   = (const float*)d_in[10];
    float* out = (float*)d_out;

    float *qp, *kp, *vt, *op, *xq, *xk, *xv, *w1, *w2;
    cudaGetSymbolAddress((void**)&qp, g_Q);
    cudaGetSymbolAddress((void**)&kp, g_K);
    cudaGetSymbolAddress((void**)&vt, g_Vt);
    cudaGetSymbolAddress((void**)&op, g_O);
    cudaGetSymbolAddress((void**)&xq, g_xq);
    cudaGetSymbolAddress((void**)&xk, g_xk);
    cudaGetSymbolAddress((void**)&xv, g_xv);
    cudaGetSymbolAddress((void**)&w1, g_w1);
    cudaGetSymbolAddress((void**)&w2, g_w2);

    cudaFuncSetAttribute(attn_tf32_kernel,
                         cudaFuncAttributeMaxDynamicSharedMemorySize,
                         ATTN_SMEM_BYTES);
    cudaFuncSetAttribute(gemm_tf32_async<0>,
                         cudaFuncAttributeMaxDynamicSharedMemorySize, G_SMEM_BYTES);
    cudaFuncSetAttribute(gemm_tf32_async<1>,
                         cudaFuncAttributeMaxDynamicSharedMemorySize, G_SMEM_BYTES);
    cudaFuncSetAttribute(gemm_tf32_async<2>,
                         cudaFuncAttributeMaxDynamicSharedMemorySize, G_SMEM_BYTES);

    // --- tf32 pre-rounding of all GEMM inputs ---
    const int n4_act = (MTOT * EMBED) / 4;          // 1048576
    round_tf32_kernel<<<1024, 256>>>((const float4*)query, (float4*)xq, n4_act);
    round_tf32_kernel<<<1024, 256>>>((const float4*)key,   (float4*)xk, n4_act);
    round_tf32_kernel<<<1024, 256>>>((const float4*)value, (float4*)xv, n4_act);
    round_tf32_kernel<<<1024, 256>>>((const float4*)in_w,  (float4*)w1, (3 * 1024 * 1024) / 4);
    round_tf32_kernel<<<1024, 256>>>((const float4*)out_w, (float4*)w2, (1024 * 1024) / 4);

    dim3 gblk(256);
    dim3 ggrid(EMBED / 128, MTOT / 128);   // (8, 32)

    // QKV projections (Q/K tf32-rounded natural; V tf32-rounded transposed)
    gemm_tf32_async<1><<<ggrid, gblk, G_SMEM_BYTES>>>(xq, w1,                   in_b,        qp, MTOT, EMBED, EMBED);
    gemm_tf32_async<1><<<ggrid, gblk, G_SMEM_BYTES>>>(xk, w1 + 1024 * 1024,     in_b + 1024, kp, MTOT, EMBED, EMBED);
    gemm_tf32_async<2><<<ggrid, gblk, G_SMEM_BYTES>>>(xv, w1 + 2 * 1024 * 1024, in_b + 2048, vt, MTOT, EMBED, EMBED);

    // Fused differential attention (ldmatrix operand loads)
    dim3 agrid(SEQ / 64, BATCH * NHEADS);  // (32, 32)
    attn_tf32_kernel<<<agrid, 128, ATTN_SMEM_BYTES>>>(qp, kp, vt, lq1, lk1, lq2, lk2, op);

    // Output projection -> d_out (raw f32 output)
    gemm_tf32_async<0><<<ggrid, gblk, G_SMEM_BYTES>>>(op, w2, out_b, out, MTOT, EMBED, EMBED);
}

// round 17
// speedup vs baseline: 1.5274x; 1.3983x over previous
#include <cuda_runtime.h>
#include <cuda_fp16.h>
#include <math.h>
#include <stdint.h>

// Problem constants
#define EMBED   1024
#define BATCH   2
#define SEQ     2048
#define NHEADS  16
#define HD      64
#define SD      32
#define MTOT    (BATCH*SEQ)          // 4096
#define SCALING 0.17677669529663687f // 1/sqrt(32)
#define EXP2C   0.25503483f          // SCALING * log2(e)
#define LAMBDA_INIT 0.2f             // 0.8 - 0.6*exp(0)
#define ONE_MINUS_LI 0.8f

// Scratch (device globals; no runtime allocation allowed)
__device__ float  g_Q[(size_t)MTOT * EMBED];   // projected Q (tf32-rounded)
__device__ float  g_K[(size_t)MTOT * EMBED];   // projected K (tf32-rounded)
__device__ __half g_Vth[(size_t)MTOT * EMBED]; // projected V, fp16 d-major [bh][64][2048]
__device__ float  g_O[(size_t)MTOT * EMBED];   // attn out   (tf32-rounded)
__device__ float  g_xq[(size_t)MTOT * EMBED];
__device__ float  g_xk[(size_t)MTOT * EMBED];
__device__ float  g_xv[(size_t)MTOT * EMBED];
__device__ float  g_w1[3 * 1024 * 1024];
__device__ float  g_w2[1024 * 1024];

// ---------------------------------------------------------------------------
// Helpers
// ---------------------------------------------------------------------------
__device__ __forceinline__ uint32_t f2tf(float x) {
    uint32_t r;
    asm("cvt.rna.tf32.f32 %0, %1;" : "=r"(r) : "f"(x));
    return r;
}
__device__ __forceinline__ uint4 cvt4(float4 v) {
    return make_uint4(f2tf(v.x), f2tf(v.y), f2tf(v.z), f2tf(v.w));
}
__device__ __forceinline__ float ex2(float x) {
    float r;
    asm("ex2.approx.f32 %0, %1;" : "=f"(r) : "f"(x));
    return r;
}
// pack two f32 -> f16x2 (first arg = high half, second = low half)
__device__ __forceinline__ uint32_t f22h(float hi, float lo) {
    uint32_t r;
    asm("cvt.rn.f16x2.f32 %0, %1, %2;" : "=r"(r) : "f"(hi), "f"(lo));
    return r;
}
__device__ __forceinline__ void cpasync16(uint32_t smem_addr, const void* gptr) {
    asm volatile("cp.async.cg.shared.global [%0], [%1], 16;"
                 :: "r"(smem_addr), "l"(gptr));
}
#define CP_COMMIT() asm volatile("cp.async.commit_group;")
#define CP_WAIT0()  asm volatile("cp.async.wait_group 0;")
#define CP_WAIT1()  asm volatile("cp.async.wait_group 1;")

__device__ __forceinline__ void ldsm4(uint32_t& r0, uint32_t& r1,
                                      uint32_t& r2, uint32_t& r3, uint32_t addr) {
    asm volatile("ldmatrix.sync.aligned.m8n8.x4.shared.b16 {%0,%1,%2,%3}, [%4];"
                 : "=r"(r0), "=r"(r1), "=r"(r2), "=r"(r3) : "r"(addr));
}

// tf32: D += A(16x8)*B(8x8)
__device__ __forceinline__ void mma8(float* c, const uint32_t* a,
                                     uint32_t b0, uint32_t b1) {
    asm volatile(
        "mma.sync.aligned.m16n8k8.row.col.f32.tf32.tf32.f32 "
        "{%0,%1,%2,%3}, {%4,%5,%6,%7}, {%8,%9}, {%0,%1,%2,%3};"
        : "+f"(c[0]), "+f"(c[1]), "+f"(c[2]), "+f"(c[3])
        : "r"(a[0]), "r"(a[1]), "r"(a[2]), "r"(a[3]), "r"(b0), "r"(b1));
}
// fp16: D += A(16x16)*B(16x8), f32 accumulate
__device__ __forceinline__ void mma16h(float* c, const uint32_t* a,
                                       uint32_t b0, uint32_t b1) {
    asm volatile(
        "mma.sync.aligned.m16n8k16.row.col.f32.f16.f16.f32 "
        "{%0,%1,%2,%3}, {%4,%5,%6,%7}, {%8,%9}, {%0,%1,%2,%3};"
        : "+f"(c[0]), "+f"(c[1]), "+f"(c[2]), "+f"(c[3])
        : "r"(a[0]), "r"(a[1]), "r"(a[2]), "r"(a[3]), "r"(b0), "r"(b1));
}

// ---------------------------------------------------------------------------
// Merged tf32 rounding passes (2 launches)
// ---------------------------------------------------------------------------
__global__ void round3_kernel(const float4* __restrict__ a, float4* __restrict__ oa,
                              const float4* __restrict__ b, float4* __restrict__ ob,
                              const float4* __restrict__ c, float4* __restrict__ oc,
                              int n4)
{
    const float4* src = (blockIdx.y == 0) ? a : (blockIdx.y == 1) ? b : c;
    float4* dst = (blockIdx.y == 0) ? oa : (blockIdx.y == 1) ? ob : oc;
    int i = blockIdx.x * blockDim.x + threadIdx.x;
    int stride = gridDim.x * blockDim.x;
    for (; i < n4; i += stride) {
        uint4 u = cvt4(src[i]);
        dst[i] = *(float4*)&u;
    }
}
__global__ void round2_kernel(const float4* __restrict__ a, float4* __restrict__ oa, int n4a,
                              const float4* __restrict__ b, float4* __restrict__ ob, int n4b)
{
    const float4* src = (blockIdx.y == 0) ? a : b;
    float4* dst = (blockIdx.y == 0) ? oa : ob;
    int n4 = (blockIdx.y == 0) ? n4a : n4b;
    int i = blockIdx.x * blockDim.x + threadIdx.x;
    int stride = gridDim.x * blockDim.x;
    for (; i < n4; i += stride) {
        uint4 u = cvt4(src[i]);
        dst[i] = *(float4*)&u;
    }
}

// ---------------------------------------------------------------------------
// tf32 GEMM (R14-validated): 3-stage cp.async + ldmatrix fragments.
// MODE 0: f32 out. MODE 1: tf32-rounded out. MODE 2: fp16 transposed per-head
//         d-major out into Vth[(b*16+h)*64+d][token].
// ---------------------------------------------------------------------------
#define G_BUF_WORDS (2 * 128 * 36)          // 9216 words per stage (A+W)
#define G_STAGES 3
#define G_SMEM_BYTES (G_STAGES * G_BUF_WORDS * 4)  // 110592

template<int MODE>
__global__ __launch_bounds__(256, 2) void gemm_tf32_async(
    const float* __restrict__ A, const float* __restrict__ W,
    const float* __restrict__ bias, float* __restrict__ C,
    int M, int N, int K)
{
    extern __shared__ uint32_t gsm[];
    const uint32_t smem_base = (uint32_t)__cvta_generic_to_shared(gsm);

    const int tid  = threadIdx.x;
    const int lane = tid & 31;
    const int warp = tid >> 5;
    const int g = lane >> 2;
    const int q = lane & 3;
    const int wm = warp >> 1;      // 0..3
    const int wn = warp & 1;       // 0..1
    const int m0 = blockIdx.y * 128;
    const int n0 = blockIdx.x * 128;

    const int nchunks = K >> 5;    // K/32

    auto issue = [&](int ck, int buf) {
        if (ck < nchunks) {
            const int k0 = ck * 32;
#pragma unroll
            for (int i = 0; i < 4; i++) {
                int idx = tid + i * 256;
                int row = idx >> 3;
                int kg  = idx & 7;
                uint32_t soff = (uint32_t)(buf * G_BUF_WORDS + row * 36 + kg * 4) * 4;
                cpasync16(smem_base + soff,
                          &A[(size_t)(m0 + row) * K + k0 + kg * 4]);
                cpasync16(smem_base + soff + 128 * 36 * 4,
                          &W[(size_t)(n0 + row) * K + k0 + kg * 4]);
            }
        }
        CP_COMMIT();
    };

    float c[2][8][4];
#pragma unroll
    for (int mf = 0; mf < 2; mf++)
#pragma unroll
        for (int nf = 0; nf < 8; nf++)
#pragma unroll
            for (int i = 0; i < 4; i++) c[mf][nf][i] = 0.f;

    const int lm7 = lane & 7;
    const int lb3 = (lane >> 3) & 1;
    const int lb4 = lane >> 4;
    const uint32_t a_off = (uint32_t)((wm * 32 + lm7 + 8 * lb3) * 36 + 4 * lb4) * 4;
    const uint32_t b_off = (uint32_t)((128 + wn * 64 + lm7 + 8 * lb4) * 36 + 4 * lb3) * 4;

    issue(0, 0);
    issue(1, 1);

    for (int it = 0; it < nchunks; it++) {
        CP_WAIT1();
        __syncthreads();
        issue(it + 2, (it + 2) % G_STAGES);

        const uint32_t stage = smem_base + (uint32_t)((it % G_STAGES) * G_BUF_WORDS) * 4;

#pragma unroll
        for (int ks = 0; ks < 4; ks++) {
            const uint32_t kcol = (uint32_t)(ks * 8) * 4;
            uint32_t a[2][4];
#pragma unroll
            for (int mf = 0; mf < 2; mf++)
                ldsm4(a[mf][0], a[mf][1], a[mf][2], a[mf][3],
                      stage + a_off + (uint32_t)(mf * 16 * 36) * 4 + kcol);
#pragma unroll
            for (int np = 0; np < 4; np++) {
                uint32_t b0, b1, b2, b3;
                ldsm4(b0, b1, b2, b3,
                      stage + b_off + (uint32_t)(np * 16 * 36) * 4 + kcol);
                mma8(c[0][2 * np + 0], a[0], b0, b1);
                mma8(c[1][2 * np + 0], a[1], b0, b1);
                mma8(c[0][2 * np + 1], a[0], b2, b3);
                mma8(c[1][2 * np + 1], a[1], b2, b3);
            }
        }
    }

#pragma unroll
    for (int mf = 0; mf < 2; mf++) {
#pragma unroll
        for (int nf = 0; nf < 8; nf++) {
            int col = n0 + wn * 64 + nf * 8 + 2 * q;
            float b0 = bias[col];
            float b1 = bias[col + 1];
#pragma unroll
            for (int half = 0; half < 2; half++) {
                int row = m0 + wm * 32 + mf * 16 + g + half * 8;
                float vx = c[mf][nf][half * 2 + 0] + b0;
                float vy = c[mf][nf][half * 2 + 1] + b1;
                if (MODE == 0) {
                    float2 o; o.x = vx; o.y = vy;
                    *(float2*)&C[(size_t)row * N + col] = o;
                } else if (MODE == 1) {
                    float2 o;
                    o.x = __uint_as_float(f2tf(vx));
                    o.y = __uint_as_float(f2tf(vy));
                    *(float2*)&C[(size_t)row * N + col] = o;
                } else {
                    // MODE 2: fp16 transposed per-head d-major write
                    __half* Ch = reinterpret_cast<__half*>(C);
                    int h  = col >> 6;
                    int dd = col & 63;
                    int bb = row >> 11;
                    int tok = row & 2047;
                    size_t vt = ((size_t)(bb * 16 + h) * 64 + dd) * SEQ + tok;
                    Ch[vt]       = __float2half(vx);
                    Ch[vt + SEQ] = __float2half(vy);
                }
            }
        }
    }
}

// ---------------------------------------------------------------------------
// Fused differential attention: QK^T in tf32 (scores bit-identical to R14),
// AV in fp16 m16n8k16 (P packed fp16, V fp16 d-major from the projection).
// fp16 tiles use 144B row stride (16B-aligned rows, conflict-free ldmatrix).
// Smem (bytes): K 2x17408, V 2x9216, P 8x2304. Total 71680.
// ---------------------------------------------------------------------------
#define AKB(buf)  ((buf) * 17408)
#define AVB(buf)  (34816 + (buf) * 9216)
#define APB       53248
#define ATTN_SMEM_BYTES 71680

__global__ __launch_bounds__(128, 2) void attn_tf32_kernel(
    const float* __restrict__ Qp, const float* __restrict__ Kp,
    const __half* __restrict__ Vth,
    const float* __restrict__ lq1, const float* __restrict__ lk1,
    const float* __restrict__ lq2, const float* __restrict__ lk2,
    float* __restrict__ O)
{
    extern __shared__ uint32_t smu[];
    const uint32_t smem_base = (uint32_t)__cvta_generic_to_shared(smu);
    __shared__ float s_lam;

    const int tid  = threadIdx.x;
    const int lane = tid & 31;
    const int warp = tid >> 5;       // 0..3
    const int g = lane >> 2;         // 0..7
    const int q = lane & 3;          // 0..3
    const int qbase = warp * 16;

    const int t0 = blockIdx.x * 64;
    const int bh = blockIdx.y;       // b*16 + h
    const int b = bh >> 4;
    const int h = bh & 15;
    const size_t base = (size_t)b * SEQ * EMBED + (size_t)h * HD;
    const size_t vtbase = (size_t)bh * 64 * SEQ;

    // K tile: 64 rows x 272B tf32. V tile: 64 d-rows x 144B fp16 (128B data).
    auto issue_tile = [&](int tile, int buf) {
        const int s0 = tile * 64;
        const size_t krow = base + (size_t)s0 * EMBED;
#pragma unroll
        for (int i = 0; i < 12; i++) {
            int idx = tid + i * 128;            // 0..1535
            if (idx < 1024) {
                int row = idx >> 4;             // 0..63
                int dg  = idx & 15;             // 16B chunk
                cpasync16(smem_base + AKB(buf) + (uint32_t)(row * 272 + dg * 16),
                          &Kp[krow + (size_t)row * EMBED + dg * 4]);
            } else {
                int j = idx - 1024;             // 0..511
                int row = j >> 3;               // d 0..63
                int ch  = j & 7;                // 8-key fp16 chunk (16B)
                cpasync16(smem_base + AVB(buf) + (uint32_t)(row * 144 + ch * 16),
                          &Vth[vtbase + (size_t)row * SEQ + s0 + ch * 8]);
            }
        }
        CP_COMMIT();
    };

    issue_tile(0, 0);

    if (tid < 32) {
        float p1 = 0.f, p2 = 0.f;
        if (tid < SD) {
            p1 = lq1[tid] * lk1[tid];
            p2 = lq2[tid] * lk2[tid];
        }
#pragma unroll
        for (int m = 16; m >= 1; m >>= 1) {
            p1 += __shfl_xor_sync(0xffffffffu, p1, m);
            p2 += __shfl_xor_sync(0xffffffffu, p2, m);
        }
        if (tid == 0) s_lam = __expf(p1) - __expf(p2) + LAMBDA_INIT;
    }

    // Q A-fragments in registers (tf32, pre-rounded)
    uint32_t qa[2][4][4];
    {
        const float* qr0 = &Qp[base + (size_t)(t0 + qbase + g) * EMBED];
        const float* qr1 = &Qp[base + (size_t)(t0 + qbase + g + 8) * EMBED];
#pragma unroll
        for (int br = 0; br < 2; br++)
#pragma unroll
            for (int ks = 0; ks < 4; ks++) {
                int d = br * 32 + ks * 8 + q;
                qa[br][ks][0] = __float_as_uint(qr0[d]);
                qa[br][ks][1] = __float_as_uint(qr1[d]);
                qa[br][ks][2] = __float_as_uint(qr0[d + 4]);
                qa[br][ks][3] = __float_as_uint(qr1[d + 4]);
            }
    }

    float acc1[8][4], acc2[8][4];
    float z[2][2];
#pragma unroll
    for (int nf = 0; nf < 8; nf++)
#pragma unroll
        for (int i = 0; i < 4; i++) { acc1[nf][i] = 0.f; acc2[nf][i] = 0.f; }
    z[0][0] = z[0][1] = z[1][0] = z[1][1] = 0.f;

    const int lm7 = lane & 7;
    const int lb3 = (lane >> 3) & 1;
    const int lb4 = lane >> 4;
    // K (tf32, 272B rows): B-frag offsets
    const uint32_t kv_off   = (uint32_t)((lm7 + 8 * lb4) * 272 + 16 * lb3);
    // V (fp16, 144B rows): B-frag offsets (n rows = d, k cols = keys)
    const uint32_t v16_off  = (uint32_t)((lm7 + 8 * lb4) * 144 + 16 * lb3);
    // P (fp16, 144B rows): A-frag offsets (rows = q, cols = keys)
    const uint32_t pa16_off = (uint32_t)((lm7 + 8 * lb3) * 144 + 16 * lb4);

    const uint32_t p1byte = APB + (uint32_t)(warp * 2 + 0) * 2304;
    const uint32_t p2byte = APB + (uint32_t)(warp * 2 + 1) * 2304;
    const uint32_t p1addr = smem_base + p1byte + pa16_off;
    const uint32_t p2addr = smem_base + p2byte + pa16_off;

    for (int it = 0; it < SEQ / 64; it++) {
        CP_WAIT0();
        __syncthreads();
        if (it + 1 < SEQ / 64) issue_tile(it + 1, (it + 1) & 1);

        const uint32_t kaddr = smem_base + AKB(it & 1) + kv_off;
        const uint32_t vaddr = smem_base + AVB(it & 1) + v16_off;

        // ---- S phase (tf32, unchanged math) ----
#pragma unroll
        for (int br = 0; br < 2; br++) {
            const uint32_t pbw = (br ? p2byte : p1byte) >> 2;   // word index base

            float s[8][4];
#pragma unroll
            for (int nf = 0; nf < 8; nf++)
#pragma unroll
                for (int i = 0; i < 4; i++) s[nf][i] = 0.f;

#pragma unroll
            for (int ks = 0; ks < 4; ks++) {
                const uint32_t dcol = (uint32_t)(br * 32 + ks * 8) * 4;
#pragma unroll
                for (int nfp = 0; nfp < 4; nfp++) {
                    uint32_t r0, r1, r2, r3;
                    ldsm4(r0, r1, r2, r3,
                          kaddr + (uint32_t)(nfp * 16 * 272) + dcol);
                    mma8(s[2 * nfp + 0], qa[br][ks], r0, r1);
                    mma8(s[2 * nfp + 1], qa[br][ks], r2, r3);
                }
            }

            // exp2 -> fp16-packed P (keys 2q,2q+1 per word) + row sums
            float rs0 = 0.f, rs1 = 0.f;
#pragma unroll
            for (int nf = 0; nf < 8; nf++) {
                float e0 = ex2(s[nf][0] * EXP2C);
                float e1 = ex2(s[nf][1] * EXP2C);
                float e2 = ex2(s[nf][2] * EXP2C);
                float e3 = ex2(s[nf][3] * EXP2C);
                rs0 += e0 + e1;
                rs1 += e2 + e3;
                smu[pbw + 36 * g + 4 * nf + q]       = f22h(e1, e0);
                smu[pbw + 36 * (g + 8) + 4 * nf + q] = f22h(e3, e2);
            }
            rs0 += __shfl_xor_sync(0xffffffffu, rs0, 1);
            rs0 += __shfl_xor_sync(0xffffffffu, rs0, 2);
            rs1 += __shfl_xor_sync(0xffffffffu, rs1, 1);
            rs1 += __shfl_xor_sync(0xffffffffu, rs1, 2);
            z[br][0] += rs0;
            z[br][1] += rs1;
        }
        __syncwarp();   // P writes visible within warp

        // ---- AV phase (fp16 m16n8k16; V frags shared across branches) ----
#pragma unroll
        for (int kc = 0; kc < 4; kc++) {
            const uint32_t kcol = (uint32_t)kc * 32;   // 16 keys = 32B fp16
            uint32_t aP1[4], aP2[4];
            ldsm4(aP1[0], aP1[1], aP1[2], aP1[3], p1addr + kcol);
            ldsm4(aP2[0], aP2[1], aP2[2], aP2[3], p2addr + kcol);
#pragma unroll
            for (int nfp = 0; nfp < 4; nfp++) {
                uint32_t v0, v1, v2, v3;
                ldsm4(v0, v1, v2, v3,
                      vaddr + (uint32_t)(nfp * 16 * 144) + kcol);
                mma16h(acc1[2 * nfp + 0], aP1, v0, v1);
                mma16h(acc1[2 * nfp + 1], aP1, v2, v3);
                mma16h(acc2[2 * nfp + 0], aP2, v0, v1);
                mma16h(acc2[2 * nfp + 1], aP2, v2, v3);
            }
        }
        __syncwarp();   // P reads done before next tile's P writes
    }

    // Epilogue: out = round_tf32( 0.8*(acc1/Z1 - lam*acc2/Z2) )
    const float lam = s_lam;
    float i1[2], i2[2];
#pragma unroll
    for (int half = 0; half < 2; half++) {
        i1[half] = ONE_MINUS_LI / z[0][half];
        i2[half] = ONE_MINUS_LI * lam / z[1][half];
    }
#pragma unroll
    for (int nf = 0; nf < 8; nf++) {
        int col = nf * 8 + 2 * q;
#pragma unroll
        for (int half = 0; half < 2; half++) {
            int row = t0 + qbase + g + half * 8;
            float vx = acc1[nf][half * 2 + 0] * i1[half] - acc2[nf][half * 2 + 0] * i2[half];
            float vy = acc1[nf][half * 2 + 1] * i1[half] - acc2[nf][half * 2 + 1] * i2[half];
            float2 o;
            o.x = __uint_as_float(f2tf(vx));
            o.y = __uint_as_float(f2tf(vy));
            *(float2*)&O[base + (size_t)row * EMBED + col] = o;
        }
    }
}

// ---------------------------------------------------------------------------
// Host launch. Order: round3(0), round2(1), gemmQ(2), gemmK(3), gemmV(4),
// attn(5), gemmO(6)  -> ncu -s 5 -c 1 captures the attention kernel.
// ---------------------------------------------------------------------------
extern "C" void kernel_launch(void* const* d_in, const int* in_sizes, int n_in,
                              void* d_out, int out_size)
{
    const float* query = (const float*)d_in[0];
    const float* key   = (const float*)d_in[1];
    const float* value = (const float*)d_in[2];
    const float* in_w  = (const float*)d_in[3];   // [3072][1024]
    const float* in_b  = (const float*)d_in[4];   // [3072]
    const float* out_w = (const float*)d_in[5];   // [1024][1024]
    const float* out_b = (const float*)d_in[6];   // [1024]
    const float* lq1   = (const float*)d_in[7];
    const float* lk1   = (const float*)d_in[8];
    const float* lq2   = (const float*)d_in[9];
    const float* lk2   = (const float*)d_in[10];
    float* out = (float*)d_out;

    float *qp, *kp, *op, *xq, *xk, *xv, *w1, *w2;
    __half* vth;
    cudaGetSymbolAddress((void**)&qp, g_Q);
    cudaGetSymbolAddress((void**)&kp, g_K);
    cudaGetSymbolAddress((void**)&vth, g_Vth);
    cudaGetSymbolAddress((void**)&op, g_O);
    cudaGetSymbolAddress((void**)&xq, g_xq);
    cudaGetSymbolAddress((void**)&xk, g_xk);
    cudaGetSymbolAddress((void**)&xv, g_xv);
    cudaGetSymbolAddress((void**)&w1, g_w1);
    cudaGetSymbolAddress((void**)&w2, g_w2);

    cudaFuncSetAttribute(attn_tf32_kernel,
                         cudaFuncAttributeMaxDynamicSharedMemorySize,
                         ATTN_SMEM_BYTES);
    cudaFuncSetAttribute(gemm_tf32_async<0>,
                         cudaFuncAttributeMaxDynamicSharedMemorySize, G_SMEM_BYTES);
    cudaFuncSetAttribute(gemm_tf32_async<1>,
                         cudaFuncAttributeMaxDynamicSharedMemorySize, G_SMEM_BYTES);
    cudaFuncSetAttribute(gemm_tf32_async<2>,
                         cudaFuncAttributeMaxDynamicSharedMemorySize, G_SMEM_BYTES);

    // tf32 pre-rounding (2 launches)
    const int n4_act = (MTOT * EMBED) / 4;          // 1048576
    round3_kernel<<<dim3(512, 3), 256>>>(
        (const float4*)query, (float4*)xq,
        (const float4*)key,   (float4*)xk,
        (const float4*)value, (float4*)xv, n4_act);
    round2_kernel<<<dim3(512, 2), 256>>>(
        (const float4*)in_w,  (float4*)w1, (3 * 1024 * 1024) / 4,
        (const float4*)out_w, (float4*)w2, (1024 * 1024) / 4);

    dim3 gblk(256);
    dim3 ggrid(EMBED / 128, MTOT / 128);   // (8, 32)

    // QKV projections (Q/K tf32-rounded natural; V fp16 transposed d-major)
    gemm_tf32_async<1><<<ggrid, gblk, G_SMEM_BYTES>>>(xq, w1,                   in_b,        qp, MTOT, EMBED, EMBED);
    gemm_tf32_async<1><<<ggrid, gblk, G_SMEM_BYTES>>>(xk, w1 + 1024 * 1024,     in_b + 1024, kp, MTOT, EMBED, EMBED);
    gemm_tf32_async<2><<<ggrid, gblk, G_SMEM_BYTES>>>(xv, w1 + 2 * 1024 * 1024, in_b + 2048, (float*)vth, MTOT, EMBED, EMBED);

    // Fused differential attention (launch index 5 for ncu)
    dim3 agrid(SEQ / 64, BATCH * NHEADS);  // (32, 32)
    attn_tf32_kernel<<<agrid, 128, ATTN_SMEM_BYTES>>>(qp, kp, vth, lq1, lk1, lq2, lk2, op);

    // Output projection -> d_out
    gemm_tf32_async<0><<<ggrid, gblk, G_SMEM_BYTES>>>(op, w2, out_b, out, MTOT, EMBED, EMBED);
}